// round 17
// baseline (speedup 1.0000x reference)
#include <cuda_runtime.h>
#include <float.h>
#include <stdint.h>

#define NB 32
#define NS 512
#define NH 1024
#define NCAND 256
#define NL 34
#define NHC 32      // half-chunks per sequence
#define HSZ 16      // tokens per half-chunk
#define SPLIT 8     // K-split (warps per gemm block)
#define KS (2 * NH / SPLIT)   // 256 floats per split
#define WTB 288               // W-transpose blocks (first in A's grid)
#define CELLS (NB * NHC)      // 1024 TMA cells
#define TILE_BYTES (HSZ * NH * 4)   // 65536

// Scratch (__device__ globals; no allocation allowed)
__device__ float g_cmax[NB * NHC * NH];          // 4 MB half-chunk maxes
__device__ float g_plp[NCAND * NH];
__device__ float g_prp[NCAND * NH];
__device__ float g_pooled[NCAND * 2 * NH];
__device__ float g_Wt[36 * 2 * NH];              // W transposed+padded [36][2048]

__device__ __forceinline__ float4 f4max(float4 a, float4 b) {
    float4 r;
    r.x = fmaxf(a.x, b.x);
    r.y = fmaxf(a.y, b.y);
    r.z = fmaxf(a.z, b.z);
    r.w = fmaxf(a.w, b.w);
    return r;
}
__device__ __forceinline__ float2 f2max(float2 a, float2 b) {
    float2 r;
    r.x = fmaxf(a.x, b.x);
    r.y = fmaxf(a.y, b.y);
    return r;
}
__device__ __forceinline__ uint32_t smem_u32(const void* p) {
    uint32_t a;
    asm("{ .reg .u64 t; cvta.to.shared.u64 t, %1; cvt.u32.u64 %0, t; }"
        : "=r"(a) : "l"(p));
    return a;
}

// ---------------------------------------------------------------------------
// Kernel A: TMA-bulk chunkmax. Block = (b, half-chunk): ONE cp.async.bulk
// puts the whole 64 KB tile in flight (no LDG-queue cap, no payload regs),
// mbarrier wait, then conflict-free LDS.128 compute. Candidate matching runs
// under the TMA latency; in-half-chunk partials (r = cut & 15) re-read smem.
// 3 blocks/SM co-resident (64 KB each) overlap TMA of one block with compute
// of another. W-transpose blocks go FIRST so their latency hides in the
// stream, and the grid tail is pure TMA cells.
// ---------------------------------------------------------------------------
__global__ void k_A(const float* __restrict__ hidden,
                    const float* __restrict__ W,
                    const int* __restrict__ cb,
                    const int* __restrict__ cc) {
    extern __shared__ __align__(16) float sm[];  // 16 x 1024 floats = 64 KB
    __shared__ __align__(8) unsigned long long mbar;
    __shared__ int s_cnt;
    __shared__ int s_n[NCAND];
    __shared__ int s_r[NCAND];

    int bid = blockIdx.x;
    int tid = threadIdx.x;

    if (bid < WTB) {    // ---- W transpose part ----
        int idx = bid * 256 + tid;
        int l = idx >> 11;
        int k = idx & (2 * NH - 1);
        g_Wt[idx] = (l < NL) ? W[(size_t)k * NL + l] : 0.f;
        return;
    }

    int cell = bid - WTB;
    int b = cell >> 5;
    int hq = cell & 31;

    uint32_t smaddr = smem_u32(sm);
    uint32_t mbaddr = smem_u32(&mbar);

    if (tid == 0) {
        asm volatile("mbarrier.init.shared.b64 [%0], 1;" :: "r"(mbaddr) : "memory");
        s_cnt = 0;
    }
    __syncthreads();

    if (tid == 0) {
        asm volatile("mbarrier.arrive.expect_tx.shared.b64 _, [%0], %1;"
                     :: "r"(mbaddr), "r"((uint32_t)TILE_BYTES) : "memory");
        const float* src = hidden + ((size_t)(b * NS + hq * HSZ)) * NH;
        asm volatile(
            "cp.async.bulk.shared::cluster.global.mbarrier::complete_tx::bytes "
            "[%0], [%1], %2, [%3];"
            :: "r"(smaddr), "l"(src), "r"((uint32_t)TILE_BYTES), "r"(mbaddr)
            : "memory");
    }

    // ---- candidate matching under TMA latency ----
    {
        int cn = cc[tid];           // tid in [0,256) == NCAND
        if (cb[tid] == b && (cn >> 4) == hq) {
            int p = atomicAdd(&s_cnt, 1);
            s_n[p] = tid;
            s_r[p] = cn & 15;
        }
    }
    __syncthreads();                // s_cnt/s_n coherent

    // ---- wait for the bulk copy (acquire orders subsequent smem reads) ----
    {
        uint32_t done;
        asm volatile(
            "{\n\t.reg .pred p;\n\t"
            "mbarrier.try_wait.parity.acquire.cta.shared::cta.b64 p, [%1], 0;\n\t"
            "selp.b32 %0, 1, 0, p;\n\t}"
            : "=r"(done) : "r"(mbaddr) : "memory");
        while (!done) {
            asm volatile(
                "{\n\t.reg .pred p;\n\t"
                "mbarrier.try_wait.parity.acquire.cta.shared::cta.b64 p, [%1], 0, 0x989680;\n\t"
                "selp.b32 %0, 1, 0, p;\n\t}"
                : "=r"(done) : "r"(mbaddr) : "memory");
        }
    }

    // ---- compute: thread owns 4 h; 16 conflict-free LDS.128 ----
    const float4* s4 = (const float4*)sm;       // [16][256]
    float4 m = make_float4(-FLT_MAX, -FLT_MAX, -FLT_MAX, -FLT_MAX);
#pragma unroll
    for (int k = 0; k < HSZ; k++) m = f4max(m, s4[k * 256 + tid]);
    ((float4*)(g_cmax + ((size_t)b * NHC + hq) * NH))[tid] = m;

    int cnt = s_cnt;
    for (int j = 0; j < cnt; j++) {
        int n = s_n[j];
        int r = s_r[j];
        float4 ml = make_float4(-FLT_MAX, -FLT_MAX, -FLT_MAX, -FLT_MAX);
        float4 mr = ml;
#pragma unroll
        for (int k = 0; k < HSZ; k++) {
            float4 v = s4[k * 256 + tid];
            if (k < r) ml = f4max(ml, v);
            else       mr = f4max(mr, v);
        }
        ((float4*)(g_plp + (size_t)n * NH))[tid] = ml;
        ((float4*)(g_prp + (size_t)n * NH))[tid] = mr;
    }
}

// ---------------------------------------------------------------------------
// Kernel B: register-predicated prefix/suffix over the 32 half-chunk maxes
// (float2, no big smem), emit pooled per candidate. Grid 64 cells.
// ---------------------------------------------------------------------------
__global__ void k_scan_combine(const int* __restrict__ cb,
                               const int* __restrict__ cc) {
    __shared__ int s_cnt;
    __shared__ int s_n[NCAND];
    __shared__ int s_q[NCAND];

    int tid = threadIdx.x;
    int b = blockIdx.x >> 1;
    int hb = blockIdx.x & 1;
    int h2 = hb * 256 + tid;        // float2 index

    if (tid == 0) s_cnt = 0;
    __syncthreads();
    if (cb[tid] == b) {
        int p = atomicAdd(&s_cnt, 1);
        s_n[p] = tid;
        s_q[p] = cc[tid] >> 4;      // owning half-chunk
    }

    const float2* cm = (const float2*)(g_cmax + (size_t)b * NHC * NH) + h2;
    float2 v[NHC];
#pragma unroll
    for (int q = 0; q < NHC; q++) v[q] = cm[q * (NH / 2)];
    __syncthreads();

    int cnt = s_cnt;
    for (int j = 0; j < cnt; j++) {
        int n = s_n[j];
        int qj = s_q[j];
        float2 pl = make_float2(-FLT_MAX, -FLT_MAX);
        float2 pr = pl;
#pragma unroll
        for (int q = 0; q < NHC; q++) {
            if (q < qj) pl = f2max(pl, v[q]);
            if (q > qj) pr = f2max(pr, v[q]);
        }
        pl = f2max(pl, ((const float2*)(g_plp + (size_t)n * NH))[h2]);
        pr = f2max(pr, ((const float2*)(g_prp + (size_t)n * NH))[h2]);
        ((float2*)(g_pooled + (size_t)n * (2 * NH)))[h2] = pl;
        ((float2*)(g_pooled + (size_t)n * (2 * NH) + NH))[h2] = pr;
    }
}

// ---------------------------------------------------------------------------
// Kernel C: gemm with fused K-reduction (proven). Block = (cand-oct,
// label-quad); 8 warps = K-splits of one output tile; reduce in smem.
// ---------------------------------------------------------------------------
__global__ __launch_bounds__(256) void k_gemm(const float* __restrict__ bias,
                                              float* __restrict__ out) {
    __shared__ float sp[SPLIT][32];
    int wid = threadIdx.x >> 5;
    int lane = threadIdx.x & 31;
    int co = blockIdx.x;
    int lq = blockIdx.y;
    int kbase = wid * KS;

    const float4* A = (const float4*)(g_pooled + (size_t)(co * 8) * (2 * NH) + kbase);
    const float4* Wt = (const float4*)(g_Wt + (size_t)(lq * 4) * (2 * NH) + kbase);
    const int rs = (2 * NH) / 4;

    float acc[8][4];
#pragma unroll
    for (int c = 0; c < 8; c++)
#pragma unroll
        for (int l = 0; l < 4; l++) acc[c][l] = 0.f;

#pragma unroll
    for (int step = 0; step < KS / 128; step++) {
        int i = lane + step * 32;
        float4 a[8], w[4];
#pragma unroll
        for (int c = 0; c < 8; c++) a[c] = A[c * rs + i];
#pragma unroll
        for (int l = 0; l < 4; l++) w[l] = Wt[l * rs + i];
#pragma unroll
        for (int c = 0; c < 8; c++)
#pragma unroll
            for (int l = 0; l < 4; l++) {
                acc[c][l] += a[c].x * w[l].x;
                acc[c][l] += a[c].y * w[l].y;
                acc[c][l] += a[c].z * w[l].z;
                acc[c][l] += a[c].w * w[l].w;
            }
    }

#pragma unroll
    for (int c = 0; c < 8; c++)
#pragma unroll
        for (int l = 0; l < 4; l++) {
            float s = acc[c][l];
#pragma unroll
            for (int o = 16; o; o >>= 1) s += __shfl_xor_sync(0xffffffffu, s, o);
            if (lane == 0) sp[wid][c * 4 + l] = s;
        }
    __syncthreads();

    if (threadIdx.x < 32) {
        int c = threadIdx.x >> 2;
        int l = threadIdx.x & 3;
        int label = lq * 4 + l;
        if (label < NL) {
            float s = bias[label];
#pragma unroll
            for (int w = 0; w < SPLIT; w++) s += sp[w][threadIdx.x];
            out[(size_t)(co * 8 + c) * NL + label] = s;
        }
    }
}

// ---------------------------------------------------------------------------
extern "C" void kernel_launch(void* const* d_in, const int* in_sizes, int n_in,
                              void* d_out, int out_size) {
    const float* hidden = (const float*)d_in[0];
    const float* W = (const float*)d_in[1];
    const float* bias = (const float*)d_in[2];
    const int* cb = (const int*)d_in[3];
    const int* cc = (const int*)d_in[4];
    float* out = (float*)d_out;

    // Opt-in to 64 KB dynamic smem (idempotent; not a stream op).
    static int configured = 0;
    if (!configured) {
        cudaFuncSetAttribute(k_A, cudaFuncAttributeMaxDynamicSharedMemorySize,
                             TILE_BYTES);
        cudaFuncSetAttribute(k_A, cudaFuncAttributePreferredSharedMemoryCarveout,
                             100);
        configured = 1;
    }

    k_A<<<WTB + CELLS, 256, TILE_BYTES>>>(hidden, W, cb, cc);

    k_scan_combine<<<NB * 2, 256>>>(cb, cc);

    dim3 gC(32, 9);
    k_gemm<<<gC, 256>>>(bias, out);
}